// round 6
// baseline (speedup 1.0000x reference)
#include <cuda_runtime.h>
#include <cstdint>

// x (8, 3, 65536) f32 -> out (8, 3, 512) f32, farthest point sampling.
#define BATCHES 8
#define NPTS    65536
#define MOUT    512
#define CLUSTER 8                         // CTAs per batch (one cluster)
#define TPB     256
#define TPBATCH (CLUSTER * TPB)           // 2048 threads per batch
#define PPT     (NPTS / TPBATCH)          // 32 points per thread (register-resident)
#define PAIRS   (PPT / 2)                 // 16 packed f32x2 pairs

typedef unsigned long long u64;
typedef unsigned int u32;

// ---- cluster helpers (inline PTX) ----
__device__ __forceinline__ u32 cluster_rank() {
    u32 r; asm("mov.u32 %0, %%cluster_ctarank;" : "=r"(r)); return r;
}
__device__ __forceinline__ u32 smem_u32(const void* p) {
    return (u32)__cvta_generic_to_shared(p);
}
__device__ __forceinline__ void st_cluster_u64(u32 local_addr, u32 rank, u64 v) {
    u32 r;
    asm volatile("mapa.shared::cluster.u32 %0, %1, %2;" : "=r"(r) : "r"(local_addr), "r"(rank));
    asm volatile("st.shared::cluster.u64 [%0], %1;" :: "r"(r), "l"(v) : "memory");
}
__device__ __forceinline__ void mbar_arrive_cluster(u32 local_mbar, u32 rank) {
    u32 r;
    asm volatile("mapa.shared::cluster.u32 %0, %1, %2;" : "=r"(r) : "r"(local_mbar), "r"(rank));
    asm volatile("mbarrier.arrive.release.cluster.shared::cluster.b64 _, [%0];"
                 :: "r"(r) : "memory");
}
__device__ __forceinline__ void mbar_init(u32 mbar, u32 count) {
    asm volatile("mbarrier.init.shared.b64 [%0], %1;" :: "r"(mbar), "r"(count) : "memory");
}
// acquire at CLUSTER scope: makes peer CTAs' shared::cluster data stores visible.
__device__ __forceinline__ void mbar_wait_parity(u32 mbar, u32 parity) {
    u32 done;
    asm volatile(
        "{\n\t.reg .pred p;\n\t"
        "mbarrier.try_wait.parity.acquire.cluster.shared::cta.b64 p, [%1], %2;\n\t"
        "selp.b32 %0, 1, 0, p;\n\t}"
        : "=r"(done) : "r"(mbar), "r"(parity) : "memory");
    if (!done) {
        asm volatile(
            "{\n\t.reg .pred P1;\n\t"
            "WAIT_LOOP_%=:\n\t"
            "mbarrier.try_wait.parity.acquire.cluster.shared::cta.b64 P1, [%0], %1, 0x989680;\n\t"
            "@P1 bra.uni WAIT_DONE_%=;\n\t"
            "bra.uni WAIT_LOOP_%=;\n\t"
            "WAIT_DONE_%=:\n\t}"
            :: "r"(mbar), "r"(parity) : "memory");
    }
}
__device__ __forceinline__ void cluster_sync_all() {
    asm volatile("barrier.cluster.arrive.aligned;" ::: "memory");
    asm volatile("barrier.cluster.wait.aligned;"   ::: "memory");
}
// ---- packed f32x2 math (per-lane IEEE .rn, bit-identical to scalar) ----
__device__ __forceinline__ u64 f2pack(float lo, float hi) {
    u64 r; asm("mov.b64 %0, {%1, %2};" : "=l"(r) : "f"(lo), "f"(hi)); return r;
}
__device__ __forceinline__ void f2unpack(float& lo, float& hi, u64 v) {
    asm("mov.b64 {%0, %1}, %2;" : "=f"(lo), "=f"(hi) : "l"(v));
}
__device__ __forceinline__ u64 f2add(u64 a, u64 b) {
    u64 r; asm("add.rn.f32x2 %0, %1, %2;" : "=l"(r) : "l"(a), "l"(b)); return r;
}
__device__ __forceinline__ u64 f2mul(u64 a, u64 b) {
    u64 r; asm("mul.rn.f32x2 %0, %1, %2;" : "=l"(r) : "l"(a), "l"(b)); return r;
}

__global__ void __launch_bounds__(TPB, 1) __cluster_dims__(CLUSTER, 1, 1)
fps_kernel(const float* __restrict__ x, float* __restrict__ out)
{
    __shared__ u64 s_wkey[TPB / 32];        // per-warp winners
    __shared__ u64 s_cand[2][CLUSTER];      // double-buffered cluster candidates
    __shared__ __align__(8) u64 s_mbar[2];  // double-buffered cluster mbarriers

    const u32 rank = cluster_rank();
    const int b    = blockIdx.x / CLUSTER;
    const int tid  = threadIdx.x;
    const int lane = tid & 31;
    const int warp = tid >> 5;
    const int tcl  = (int)rank * TPB + tid;                // 0..2047 within batch

    const float* __restrict__ xb = x + (size_t)b * 3 * NPTS;
    float* __restrict__ ob       = out + (size_t)b * 3 * MOUT;

    // mbarrier init: one arrival from each of the 8 CTAs per phase
    if (tid == 0) {
        mbar_init(smem_u32(&s_mbar[0]), CLUSTER);
        mbar_init(smem_u32(&s_mbar[1]), CLUSTER);
    }

    // Register-resident points (packed pairs) + running min distance
    u64 px2[PAIRS], py2[PAIRS], pz2[PAIRS];
    float dist[PPT];
#pragma unroll
    for (int i = 0; i < PAIRS; i++) {
        int k0 = 2 * i, k1 = 2 * i + 1;
        int g0 = k0 * TPBATCH + tcl, g1 = k1 * TPBATCH + tcl;   // coalesced
        px2[i] = f2pack(__ldg(xb + g0),            __ldg(xb + g1));
        py2[i] = f2pack(__ldg(xb + NPTS + g0),     __ldg(xb + NPTS + g1));
        pz2[i] = f2pack(__ldg(xb + 2 * NPTS + g0), __ldg(xb + 2 * NPTS + g1));
        dist[k0] = INFINITY;
        dist[k1] = INFINITY;
    }

    // First centroid is point 0 (standard PointNet++ convention)
    float cx = __ldg(xb);
    float cy = __ldg(xb + NPTS);
    float cz = __ldg(xb + 2 * NPTS);
    if (rank == 0 && tid == 0) {
        ob[0]        = cx;
        ob[MOUT]     = cy;
        ob[2 * MOUT] = cz;
    }

    const u32 cand_base0 = smem_u32(&s_cand[0][rank]);
    const u32 cand_base1 = smem_u32(&s_cand[1][rank]);
    const u32 mbar_l0    = smem_u32(&s_mbar[0]);
    const u32 mbar_l1    = smem_u32(&s_mbar[1]);

    __syncthreads();
    cluster_sync_all();     // all mbarriers initialized before any remote arrive

    for (int j = 1; j < MOUT; j++) {
        // ---- pass 1: packed distance update. Per-lane .rn arithmetic, same
        //      order as reference: (dx*dx + dy*dy) + dz*dz. Track max only. ----
        u64 ncx = f2pack(-cx, -cx);
        u64 ncy = f2pack(-cy, -cy);
        u64 ncz = f2pack(-cz, -cz);
        float best = -1.0f;
#pragma unroll
        for (int i = 0; i < PAIRS; i++) {
            u64 dx = f2add(px2[i], ncx);
            u64 dy = f2add(py2[i], ncy);
            u64 dz = f2add(pz2[i], ncz);
            u64 s  = f2add(f2mul(dx, dx), f2mul(dy, dy));
            u64 dd = f2add(s, f2mul(dz, dz));
            float e0, e1;
            f2unpack(e0, e1, dd);
            float n0 = fminf(dist[2 * i],     e0);
            float n1 = fminf(dist[2 * i + 1], e1);
            dist[2 * i]     = n0;
            dist[2 * i + 1] = n1;
            best = fmaxf(best, fmaxf(n0, n1));
        }

        // ---- pass 2: min k among dist[k]==best (first-occurrence argmax) ----
        int kb = 0x7FFFFFFF;
#pragma unroll
        for (int k = 0; k < PPT; k++) {
            if (dist[k] == best) kb = min(kb, k);
        }
        u32 bidx = (u32)(kb * TPBATCH + tcl);

        // ---- warp reduce via REDUX: max dist bits, then min index among ties.
        //      (squared distances are >= 0, so u32 bit order == float order) ----
        u32 dbits = __float_as_uint(best);
        u32 wmax  = __reduce_max_sync(0xFFFFFFFFu, dbits);
        u32 cand  = (dbits == wmax) ? bidx : 0xFFFFFFFFu;
        u32 wmin  = __reduce_min_sync(0xFFFFFFFFu, cand);
        if (lane == 0)
            s_wkey[warp] = ((u64)wmax << 32) | (u32)~wmin;   // key: dist | ~idx
        __syncthreads();

        // ---- block reduce (warp 0, REDUX over 8 per-warp winners) ----
        if (warp == 0) {
            u32 h = 0, lo = 0;
            if (lane < (TPB / 32)) {
                u64 k = s_wkey[lane];
                h  = (u32)(k >> 32);
                lo = (u32)k;
            }
            u32 hmax = __reduce_max_sync(0xFFFFFFFFu, h);
            u32 lsel = (h == hmax) ? lo : 0u;                // max(~idx) == min idx
            u32 lmax = __reduce_max_sync(0xFFFFFFFFu, lsel);
            // ---- leader: store candidate to all ranks + arrive on their mbars ----
            if (lane == 0) {
                u64 bk = ((u64)hmax << 32) | lmax;
                u32 laddr = (j & 1) ? cand_base1 : cand_base0;
                u32 maddr = (j & 1) ? mbar_l1 : mbar_l0;
#pragma unroll
                for (int r = 0; r < CLUSTER; r++) {
                    st_cluster_u64(laddr, r, bk);
                    mbar_arrive_cluster(maddr, r);           // release.cluster
                }
            }
        }

        // ---- wait: local mbar collects one arrival from each CTA ----
        mbar_wait_parity((j & 1) ? mbar_l1 : mbar_l0, ((u32)(j - 1) >> 1) & 1);

        // ---- every thread picks global winner from 8 local candidates ----
        const u64* candp = s_cand[j & 1];
        u64 wk = candp[0];
#pragma unroll
        for (int r = 1; r < CLUSTER; r++) {
            u64 c = candp[r];
            if (c > wk) wk = c;
        }
        int widx = (int)(~(u32)wk);

        // ---- fetch winning centroid coords (L2-resident broadcast load) ----
        cx = __ldg(xb + widx);
        cy = __ldg(xb + NPTS + widx);
        cz = __ldg(xb + 2 * NPTS + widx);

        if (rank == 0 && tid == 0) {
            ob[j]            = cx;
            ob[MOUT + j]     = cy;
            ob[2 * MOUT + j] = cz;
        }
    }

    // No CTA may exit (deallocating SMEM) while peers' remote stores/arrives
    // targeting it could still be in flight.
    cluster_sync_all();
}

extern "C" void kernel_launch(void* const* d_in, const int* in_sizes, int n_in,
                              void* d_out, int out_size)
{
    const float* x = (const float*)d_in[0];
    float* out     = (float*)d_out;
    // 8 batches x cluster of 8 CTAs; __cluster_dims__ applies to plain launches.
    fps_kernel<<<BATCHES * CLUSTER, TPB>>>(x, out);
}

// round 7
// speedup vs baseline: 1.8597x; 1.8597x over previous
#include <cuda_runtime.h>
#include <cstdint>

// x (8, 3, 65536) f32 -> out (8, 3, 512) f32, farthest point sampling.
#define BATCHES 8
#define NPTS    65536
#define MOUT    512
#define CLUSTER 8                         // CTAs per batch (one cluster)
#define TPB     256
#define TPBATCH (CLUSTER * TPB)           // 2048 threads per batch
#define PPT     (NPTS / TPBATCH)          // 32 points per thread (register-resident)
#define PAIRS   (PPT / 2)                 // 16 packed f32x2 pairs

typedef unsigned long long u64;
typedef unsigned int u32;

// ---- cluster helpers (ALL mapa are asm volatile: non-volatile mapa with
//      rank=lane was if-converted to run on lanes>=8 -> invalid rank -> IMA) ----
__device__ __forceinline__ u32 cluster_rank() {
    u32 r; asm("mov.u32 %0, %%cluster_ctarank;" : "=r"(r)); return r;
}
__device__ __forceinline__ u32 smem_u32(const void* p) {
    return (u32)__cvta_generic_to_shared(p);
}
__device__ __forceinline__ void cluster_sync_all() {
    asm volatile("barrier.cluster.arrive.aligned;" ::: "memory");
    asm volatile("barrier.cluster.wait.aligned;"   ::: "memory");
}
// ---- packed f32x2 math (per-lane IEEE .rn, bit-identical to scalar) ----
__device__ __forceinline__ u64 f2pack(float lo, float hi) {
    u64 r; asm("mov.b64 %0, {%1, %2};" : "=l"(r) : "f"(lo), "f"(hi)); return r;
}
__device__ __forceinline__ void f2unpack(float& lo, float& hi, u64 v) {
    asm("mov.b64 {%0, %1}, %2;" : "=f"(lo), "=f"(hi) : "l"(v));
}
__device__ __forceinline__ u64 f2add(u64 a, u64 b) {
    u64 r; asm("add.rn.f32x2 %0, %1, %2;" : "=l"(r) : "l"(a), "l"(b)); return r;
}
__device__ __forceinline__ u64 f2mul(u64 a, u64 b) {
    u64 r; asm("mul.rn.f32x2 %0, %1, %2;" : "=l"(r) : "l"(a), "l"(b)); return r;
}

// Mailbox slot: 2 x u64 (16B): [0]=key  [1]=tag (iteration j)
__global__ void __launch_bounds__(TPB, 1) __cluster_dims__(CLUSTER, 1, 1)
fps_kernel(const float* __restrict__ x, float* __restrict__ out)
{
    __shared__ u64 s_wkey[TPB / 32];                 // per-warp winners
    __shared__ __align__(16) u64 s_slot[2][CLUSTER][2];

    const u32 rank = cluster_rank();
    const int b    = blockIdx.x / CLUSTER;
    const int tid  = threadIdx.x;
    const int lane = tid & 31;
    const int warp = tid >> 5;
    const int tcl  = (int)rank * TPB + tid;          // 0..2047 within batch

    const float* __restrict__ xb = x + (size_t)b * 3 * NPTS;
    float* __restrict__ ob       = out + (size_t)b * 3 * MOUT;

    // Register-resident points (packed pairs) + running min distance
    u64 px2[PAIRS], py2[PAIRS], pz2[PAIRS];
    float dist[PPT];
#pragma unroll
    for (int i = 0; i < PAIRS; i++) {
        int k0 = 2 * i, k1 = 2 * i + 1;
        int g0 = k0 * TPBATCH + tcl, g1 = k1 * TPBATCH + tcl;   // coalesced
        px2[i] = f2pack(__ldg(xb + g0),            __ldg(xb + g1));
        py2[i] = f2pack(__ldg(xb + NPTS + g0),     __ldg(xb + NPTS + g1));
        pz2[i] = f2pack(__ldg(xb + 2 * NPTS + g0), __ldg(xb + 2 * NPTS + g1));
        dist[k0] = INFINITY;
        dist[k1] = INFINITY;
    }

    // init mailbox tags to 0 (tags used are j = 1..511)
    if (tid < CLUSTER * 2) {
        s_slot[tid & 1][tid >> 1][1] = 0ULL;
    }

    // First centroid is point 0 (standard PointNet++ convention)
    float cx = __ldg(xb);
    float cy = __ldg(xb + NPTS);
    float cz = __ldg(xb + 2 * NPTS);
    if (rank == 0 && tid == 0) {
        ob[0]        = cx;
        ob[MOUT]     = cy;
        ob[2 * MOUT] = cz;
    }

    __syncthreads();
    cluster_sync_all();   // all tags zeroed everywhere before any mailbox store

    for (int j = 1; j < MOUT; j++) {
        // ---- pass 1: packed distance update. Per-lane .rn arithmetic, same
        //      order as reference: (dx*dx + dy*dy) + dz*dz. Track max only. ----
        u64 ncx = f2pack(-cx, -cx);
        u64 ncy = f2pack(-cy, -cy);
        u64 ncz = f2pack(-cz, -cz);
        float best = -1.0f;
#pragma unroll
        for (int i = 0; i < PAIRS; i++) {
            u64 dx = f2add(px2[i], ncx);
            u64 dy = f2add(py2[i], ncy);
            u64 dz = f2add(pz2[i], ncz);
            u64 s  = f2add(f2mul(dx, dx), f2mul(dy, dy));
            u64 dd = f2add(s, f2mul(dz, dz));
            float e0, e1;
            f2unpack(e0, e1, dd);
            float n0 = fminf(dist[2 * i],     e0);
            float n1 = fminf(dist[2 * i + 1], e1);
            dist[2 * i]     = n0;
            dist[2 * i + 1] = n1;
            best = fmaxf(best, fmaxf(n0, n1));
        }

        // ---- pass 2: min k among dist[k]==best (first-occurrence argmax) ----
        int kb = 0x7FFFFFFF;
#pragma unroll
        for (int k = 0; k < PPT; k++) {
            if (dist[k] == best) kb = min(kb, k);
        }
        int bidx = kb * TPBATCH + tcl;

        // Packed key: (dist bits << 32) | ~idx  -> max picks largest dist,
        // ties resolved to the LOWEST index (jnp.argmax first-occurrence).
        u64 key = ((u64)__float_as_uint(best) << 32) |
                  (u64)(u32)(~(u32)bidx);

        // ---- warp reduce (proven shuffle chain) ----
#pragma unroll
        for (int off = 16; off > 0; off >>= 1) {
            u64 k2 = __shfl_down_sync(0xFFFFFFFFu, key, off);
            if (k2 > key) key = k2;
        }
        if (lane == 0) s_wkey[warp] = key;
        __syncthreads();

        // ---- block reduce: warp 0 butterfly so lanes 0..7 all hold the block
        //      winner; lane r publishes {key, tag=j} into rank r's mailbox ----
        if (warp == 0) {
            u64 bk = s_wkey[lane & 7];
#pragma unroll
            for (int off = 4; off > 0; off >>= 1) {
                u64 k2 = __shfl_xor_sync(0xFFFFFFFFu, bk, off);
                if (k2 > bk) bk = k2;
            }
            if (lane < CLUSTER) {
                u32 laddr = smem_u32(&s_slot[j & 1][rank][0]);
                u32 dst;
                asm volatile("mapa.shared::cluster.u32 %0, %1, %2;"
                             : "=r"(dst) : "r"(laddr), "r"((u32)lane));
                asm volatile("st.shared::cluster.u64 [%0], %1;"
                             :: "r"(dst), "l"(bk) : "memory");
                // release orders the key store before the tag store in the
                // destination CTA's SMEM.
                asm volatile("st.release.cluster.shared::cluster.u64 [%0], %1;"
                             :: "r"(dst + 8), "l"((u64)(u32)j) : "memory");
            }
        }

        // ---- poll local mailbox tags (plain volatile LDS: SMEM is physically
        //      coherent; producer-side release gives key-before-tag order) ----
        {
            const u32 tbase = smem_u32(&s_slot[j & 1][0][0]);
            bool ready;
            do {
                ready = true;
#pragma unroll
                for (int s = 0; s < CLUSTER; s++) {
                    u64 t;
                    asm volatile("ld.volatile.shared.u64 %0, [%1];"
                                 : "=l"(t) : "r"(tbase + s * 16 + 8) : "memory");
                    ready &= (t == (u64)(u32)j);
                }
            } while (!ready);
        }

        // ---- select global winner from 8 local candidates ----
        const u64* cand = &s_slot[j & 1][0][0];
        u64 wk = cand[0];
#pragma unroll
        for (int r = 1; r < CLUSTER; r++) {
            u64 c = cand[r * 2];
            if (c > wk) wk = c;
        }
        int widx = (int)(~(u32)wk);

        // ---- fetch winning centroid coords (no cluster fence in the loop
        //      anymore -> lines can persist in L1) ----
        cx = __ldg(xb + widx);
        cy = __ldg(xb + NPTS + widx);
        cz = __ldg(xb + 2 * NPTS + widx);

        if (rank == 0 && tid == 0) {
            ob[j]            = cx;
            ob[MOUT + j]     = cy;
            ob[2 * MOUT + j] = cz;
        }
    }

    // No CTA may exit (deallocating its SMEM) while peers' remote stores
    // targeting it could still be in flight.
    cluster_sync_all();
}

extern "C" void kernel_launch(void* const* d_in, const int* in_sizes, int n_in,
                              void* d_out, int out_size)
{
    const float* x = (const float*)d_in[0];
    float* out     = (float*)d_out;
    fps_kernel<<<BATCHES * CLUSTER, TPB>>>(x, out);
}